// round 1
// baseline (speedup 1.0000x reference)
#include <cuda_runtime.h>

#define BB   4
#define TLEN 1024
#define EE   1024
#define NH   16
#define HD   64
#define SCALING 0.125f   // 64^-0.5

// ---------------- scratch (static device arrays; no runtime allocation) ----
__device__ float g_q[(size_t)BB*NH*TLEN*HD];    // 16 MB  [B,H,T,D]
__device__ float g_k[(size_t)BB*NH*TLEN*HD];    // 16 MB
__device__ float g_v[(size_t)BB*NH*TLEN*HD];    // 16 MB
__device__ float g_ctx[(size_t)BB*TLEN*EE];     // 16 MB  [B,T,E]
__device__ float g_maskval[BB*TLEN];            // 0 or -1e30 additive mask
__device__ int   g_mask_kind;                   // 0=int32, 1=uint8, 2=float32

// ---------------- mask dtype sniffing --------------------------------------
// bool input may be serialized as uint8 (itemsize 1), int32, or float32.
// Safe probe region: first 4096 bytes exist under every interpretation.
//  uint8 bools : bytes at offset 4i+1 ~half nonzero
//  int32 0/1   : only offset 4i+0 nonzero
//  f32 0.0/1.0 : offset 4i+0 and 4i+1 always zero (1.0f = 00 00 80 3f)
__global__ void detect_mask_kernel(const unsigned char* __restrict__ p) {
    __shared__ int c0s, c1s;
    if (threadIdx.x == 0) { c0s = 0; c1s = 0; }
    __syncthreads();
    int c0 = 0, c1 = 0;
    for (int i = threadIdx.x; i < 1024; i += blockDim.x) {
        if (p[4 * i + 1]) c1++;
        if (p[4 * i + 0]) c0++;
    }
    if (c0) atomicAdd(&c0s, c0);
    if (c1) atomicAdd(&c1s, c1);
    __syncthreads();
    if (threadIdx.x == 0) g_mask_kind = c1s ? 1 : (c0s ? 0 : 2);
}

__global__ void expand_mask_kernel(const void* __restrict__ p) {
    int i = blockIdx.x * blockDim.x + threadIdx.x;
    if (i >= BB * TLEN) return;
    int kind = g_mask_kind;
    bool m;
    if (kind == 1)      m = ((const unsigned char*)p)[i] != 0;
    else if (kind == 0) m = ((const int*)p)[i] != 0;
    else                m = ((const float*)p)[i] != 0.0f;
    g_maskval[i] = m ? -1e30f : 0.0f;
}

// ---------------- GEMM: C = (A @ B^T + bias) * scale -----------------------
// A [M,K] row-major, B [N,K] row-major (torch Linear weight), bias [N].
// map_bhld=1: scatter into [B,H,L,D] (L=TLEN); else plain [M,N].
// Tiles: 64x64x16, 256 threads, 4x4 register micro-tile.
__global__ void gemm_abt_kernel(const float* __restrict__ A,
                                const float* __restrict__ Bm,
                                const float* __restrict__ bias,
                                float* __restrict__ C,
                                int M, int N, int K, float scale, int map_bhld) {
    __shared__ float As[16][64];
    __shared__ float Bs[16][64];
    int tid = threadIdx.x;
    int m0 = blockIdx.x * 64, n0 = blockIdx.y * 64;
    int tx = tid & 15, ty = tid >> 4;
    int lr = tid >> 2, lc = (tid & 3) << 2;

    const float* Ap = A + (size_t)(m0 + lr) * K + lc;
    const float* Bp = Bm + (size_t)(n0 + lr) * K + lc;

    float acc[4][4] = {};
    for (int k0 = 0; k0 < K; k0 += 16) {
        float4 a4 = *(const float4*)(Ap + k0);
        float4 b4 = *(const float4*)(Bp + k0);
        As[lc + 0][lr] = a4.x; As[lc + 1][lr] = a4.y;
        As[lc + 2][lr] = a4.z; As[lc + 3][lr] = a4.w;
        Bs[lc + 0][lr] = b4.x; Bs[lc + 1][lr] = b4.y;
        Bs[lc + 2][lr] = b4.z; Bs[lc + 3][lr] = b4.w;
        __syncthreads();
#pragma unroll
        for (int kk = 0; kk < 16; kk++) {
            float af[4], bf[4];
#pragma unroll
            for (int i = 0; i < 4; i++) af[i] = As[kk][ty * 4 + i];
#pragma unroll
            for (int j = 0; j < 4; j++) bf[j] = Bs[kk][tx * 4 + j];
#pragma unroll
            for (int i = 0; i < 4; i++)
#pragma unroll
                for (int j = 0; j < 4; j++)
                    acc[i][j] += af[i] * bf[j];
        }
        __syncthreads();
    }
#pragma unroll
    for (int i = 0; i < 4; i++) {
        int m = m0 + ty * 4 + i;
#pragma unroll
        for (int j = 0; j < 4; j++) {
            int n = n0 + tx * 4 + j;
            float v = (acc[i][j] + bias[n]) * scale;
            if (map_bhld) {
                int b = m >> 10, t = m & 1023, h = n >> 6, d = n & 63;
                C[(((size_t)(b * NH + h)) * TLEN + t) * HD + d] = v;
            } else {
                C[(size_t)m * N + n] = v;
            }
        }
    }
}

// ---------------- fused flash attention ------------------------------------
struct FlashSmem {
    float Q[64][65];
    float Kt[64][65];
    float V[64][65];
    float S[64][65];
    float maskv[64];
    float mrow[64];
    float lrow[64];
    float arow[64];
};

__global__ void flash_kernel(const float* __restrict__ attn_bias) {
    extern __shared__ char smraw[];
    FlashSmem* sm = (FlashSmem*)smraw;
    int tid = threadIdx.x;
    int t0 = blockIdx.x * 64;
    int h = blockIdx.y, b = blockIdx.z;
    int bh = b * NH + h;
    const float* qbase = g_q + (size_t)bh * TLEN * HD;
    const float* kbase = g_k + (size_t)bh * TLEN * HD;
    const float* vbase = g_v + (size_t)bh * TLEN * HD;
    const float* biasbase = attn_bias + (size_t)bh * TLEN * TLEN;
    int tx = tid & 15, ty = tid >> 4;

    // Q tile [64 x 64]
#pragma unroll
    for (int rep = 0; rep < 4; rep++) {
        int idx = rep * 256 + tid;
        int r = idx >> 4, c4 = (idx & 15) << 2;
        float4 q4 = *(const float4*)(qbase + (size_t)(t0 + r) * HD + c4);
        sm->Q[r][c4 + 0] = q4.x; sm->Q[r][c4 + 1] = q4.y;
        sm->Q[r][c4 + 2] = q4.z; sm->Q[r][c4 + 3] = q4.w;
    }
    if (tid < 64) { sm->mrow[tid] = -1e30f; sm->lrow[tid] = 0.0f; }

    float acc[4][4] = {};

    for (int s0 = 0; s0 < TLEN; s0 += 64) {
        __syncthreads();  // prev PV finished before K/V/S overwritten (also makes Q/m/l visible)

        // load K, V tiles and mask slice
#pragma unroll
        for (int rep = 0; rep < 4; rep++) {
            int idx = rep * 256 + tid;
            int r = idx >> 4, c4 = (idx & 15) << 2;
            float4 k4 = *(const float4*)(kbase + (size_t)(s0 + r) * HD + c4);
            sm->Kt[r][c4 + 0] = k4.x; sm->Kt[r][c4 + 1] = k4.y;
            sm->Kt[r][c4 + 2] = k4.z; sm->Kt[r][c4 + 3] = k4.w;
            float4 v4 = *(const float4*)(vbase + (size_t)(s0 + r) * HD + c4);
            sm->V[r][c4 + 0] = v4.x; sm->V[r][c4 + 1] = v4.y;
            sm->V[r][c4 + 2] = v4.z; sm->V[r][c4 + 3] = v4.w;
        }
        if (tid < 64) sm->maskv[tid] = g_maskval[b * TLEN + s0 + tid];
        __syncthreads();

        // scores: S = Q @ K^T  (then + bias + mask)
        float sacc[4][4] = {};
#pragma unroll 8
        for (int d = 0; d < 64; d++) {
            float af[4], bf[4];
#pragma unroll
            for (int i = 0; i < 4; i++) af[i] = sm->Q[ty * 4 + i][d];
#pragma unroll
            for (int j = 0; j < 4; j++) bf[j] = sm->Kt[tx * 4 + j][d];
#pragma unroll
            for (int i = 0; i < 4; i++)
#pragma unroll
                for (int j = 0; j < 4; j++)
                    sacc[i][j] += af[i] * bf[j];
        }
#pragma unroll
        for (int i = 0; i < 4; i++) {
            int t = t0 + ty * 4 + i;
            float4 b4 = *(const float4*)(biasbase + (size_t)t * TLEN + s0 + tx * 4);
            sm->S[ty * 4 + i][tx * 4 + 0] = sacc[i][0] + b4.x + sm->maskv[tx * 4 + 0];
            sm->S[ty * 4 + i][tx * 4 + 1] = sacc[i][1] + b4.y + sm->maskv[tx * 4 + 1];
            sm->S[ty * 4 + i][tx * 4 + 2] = sacc[i][2] + b4.z + sm->maskv[tx * 4 + 2];
            sm->S[ty * 4 + i][tx * 4 + 3] = sacc[i][3] + b4.w + sm->maskv[tx * 4 + 3];
        }
        __syncthreads();

        // online softmax, one thread per query row
        if (tid < 64) {
            float m_old = sm->mrow[tid];
            float mx = m_old;
#pragma unroll 8
            for (int s = 0; s < 64; s++) mx = fmaxf(mx, sm->S[tid][s]);
            float alpha = __expf(m_old - mx);
            float sum = 0.0f;
#pragma unroll 8
            for (int s = 0; s < 64; s++) {
                float pv = __expf(sm->S[tid][s] - mx);
                sm->S[tid][s] = pv;
                sum += pv;
            }
            sm->lrow[tid] = sm->lrow[tid] * alpha + sum;
            sm->mrow[tid] = mx;
            sm->arow[tid] = alpha;
        }
        __syncthreads();

        // O = O*alpha + P @ V
        float a[4];
#pragma unroll
        for (int i = 0; i < 4; i++) a[i] = sm->arow[ty * 4 + i];
#pragma unroll
        for (int i = 0; i < 4; i++)
#pragma unroll
            for (int j = 0; j < 4; j++)
                acc[i][j] *= a[i];
#pragma unroll 8
        for (int s = 0; s < 64; s++) {
            float pf[4], vf[4];
#pragma unroll
            for (int i = 0; i < 4; i++) pf[i] = sm->S[ty * 4 + i][s];
#pragma unroll
            for (int j = 0; j < 4; j++) vf[j] = sm->V[s][tx * 4 + j];
#pragma unroll
            for (int i = 0; i < 4; i++)
#pragma unroll
                for (int j = 0; j < 4; j++)
                    acc[i][j] += pf[i] * vf[j];
        }
    }

    // epilogue: O /= l, write context in [B,T,E]
#pragma unroll
    for (int i = 0; i < 4; i++) {
        int row = ty * 4 + i;
        float linv = 1.0f / sm->lrow[row];
        float4 o4;
        o4.x = acc[i][0] * linv; o4.y = acc[i][1] * linv;
        o4.z = acc[i][2] * linv; o4.w = acc[i][3] * linv;
        size_t off = ((size_t)(b * TLEN + t0 + row)) * EE + h * HD + tx * 4;
        *(float4*)(g_ctx + off) = o4;
    }
}

// ---------------- launch ----------------------------------------------------
extern "C" void kernel_launch(void* const* d_in, const int* in_sizes, int n_in,
                              void* d_out, int out_size) {
    const float* query     = (const float*)d_in[0];
    const float* key       = (const float*)d_in[1];
    const float* value     = (const float*)d_in[2];
    const void*  mask      = d_in[3];
    const float* attn_bias = (const float*)d_in[4];
    const float* wq = (const float*)d_in[5];
    const float* bq = (const float*)d_in[6];
    const float* wk = (const float*)d_in[7];
    const float* bk = (const float*)d_in[8];
    const float* wv = (const float*)d_in[9];
    const float* bv = (const float*)d_in[10];
    const float* wo = (const float*)d_in[11];
    const float* bo = (const float*)d_in[12];
    float* out = (float*)d_out;

    void *pq, *pk, *pv, *pctx;
    cudaGetSymbolAddress(&pq, g_q);
    cudaGetSymbolAddress(&pk, g_k);
    cudaGetSymbolAddress(&pv, g_v);
    cudaGetSymbolAddress(&pctx, g_ctx);

    detect_mask_kernel<<<1, 256>>>((const unsigned char*)mask);
    expand_mask_kernel<<<(BB * TLEN + 255) / 256, 256>>>(mask);

    dim3 gg(64, 16);  // M/64=64, N/64=16
    gemm_abt_kernel<<<gg, 256>>>(query, wq, bq, (float*)pq, 4096, 1024, 1024, SCALING, 1);
    gemm_abt_kernel<<<gg, 256>>>(key,   wk, bk, (float*)pk, 4096, 1024, 1024, 1.0f, 1);
    gemm_abt_kernel<<<gg, 256>>>(value, wv, bv, (float*)pv, 4096, 1024, 1024, 1.0f, 1);

    cudaFuncSetAttribute(flash_kernel, cudaFuncAttributeMaxDynamicSharedMemorySize,
                         (int)sizeof(FlashSmem));
    flash_kernel<<<dim3(16, 16, 4), 256, sizeof(FlashSmem)>>>(attn_bias);

    gemm_abt_kernel<<<gg, 256>>>((const float*)pctx, wo, bo, out, 4096, 1024, 1024, 1.0f, 0);
}

// round 3
// speedup vs baseline: 1.5114x; 1.5114x over previous
#include <cuda_runtime.h>
#include <cuda_bf16.h>
#include <cstdint>

#define BB   4
#define TLEN 1024
#define EE   1024
#define NH   16
#define HD   64
#define SCALING 0.125f   // 64^-0.5

// ---------------- scratch (static device arrays; no runtime allocation) ----
__device__ float g_q[(size_t)BB*NH*TLEN*HD];    // 16 MB  [B,H,T,D]
__device__ float g_k[(size_t)BB*NH*TLEN*HD];    // 16 MB
__device__ float g_v[(size_t)BB*NH*TLEN*HD];    // 16 MB
__device__ float g_ctx[(size_t)BB*TLEN*EE];     // 16 MB  [B,T,E]
__device__ float g_maskval[BB*TLEN];            // 0 or -1e30 additive mask
__device__ int   g_mask_kind;                   // 0=int32, 1=uint8, 2=float32

// bf16 hi/lo split buffers
#define ACT_ELEMS (4096*1024)
#define W_ELEMS   (1024*1024)
__device__ unsigned short g_xq_h[ACT_ELEMS], g_xq_l[ACT_ELEMS];
__device__ unsigned short g_xk_h[ACT_ELEMS], g_xk_l[ACT_ELEMS];
__device__ unsigned short g_xv_h[ACT_ELEMS], g_xv_l[ACT_ELEMS];
__device__ unsigned short g_cx_h[ACT_ELEMS], g_cx_l[ACT_ELEMS];
__device__ unsigned short g_wq_h[W_ELEMS], g_wq_l[W_ELEMS];
__device__ unsigned short g_wk_h[W_ELEMS], g_wk_l[W_ELEMS];
__device__ unsigned short g_wv_h[W_ELEMS], g_wv_l[W_ELEMS];
__device__ unsigned short g_wo_h[W_ELEMS], g_wo_l[W_ELEMS];

// ---------------- warp-mma helpers (sm_80-class, legal on compute_100) -----
__device__ __forceinline__ uint32_t smem_u32(const void* p) {
    uint32_t a;
    asm("{ .reg .u64 t; cvta.to.shared.u64 t, %1; cvt.u32.u64 %0, t; }"
        : "=r"(a) : "l"(p));
    return a;
}

__device__ __forceinline__ void ldsm_x4(uint32_t r[4], uint32_t addr) {
    asm volatile("ldmatrix.sync.aligned.m8n8.x4.shared.b16 {%0,%1,%2,%3}, [%4];"
        : "=r"(r[0]), "=r"(r[1]), "=r"(r[2]), "=r"(r[3]) : "r"(addr));
}

__device__ __forceinline__ void mma_bf16(float c[4], const uint32_t a[4],
                                         const uint32_t b[2]) {
    asm volatile(
        "mma.sync.aligned.m16n8k16.row.col.f32.bf16.bf16.f32 "
        "{%0,%1,%2,%3}, {%4,%5,%6,%7}, {%8,%9}, {%0,%1,%2,%3};"
        : "+f"(c[0]), "+f"(c[1]), "+f"(c[2]), "+f"(c[3])
        : "r"(a[0]), "r"(a[1]), "r"(a[2]), "r"(a[3]), "r"(b[0]), "r"(b[1]));
}

// ---------------- mask dtype sniffing --------------------------------------
__global__ void detect_mask_kernel(const unsigned char* __restrict__ p) {
    __shared__ int c0s, c1s;
    if (threadIdx.x == 0) { c0s = 0; c1s = 0; }
    __syncthreads();
    int c0 = 0, c1 = 0;
    for (int i = threadIdx.x; i < 1024; i += blockDim.x) {
        if (p[4 * i + 1]) c1++;
        if (p[4 * i + 0]) c0++;
    }
    if (c0) atomicAdd(&c0s, c0);
    if (c1) atomicAdd(&c1s, c1);
    __syncthreads();
    if (threadIdx.x == 0) g_mask_kind = c1s ? 1 : (c0s ? 0 : 2);
}

__global__ void expand_mask_kernel(const void* __restrict__ p) {
    int i = blockIdx.x * blockDim.x + threadIdx.x;
    if (i >= BB * TLEN) return;
    int kind = g_mask_kind;
    bool m;
    if (kind == 1)      m = ((const unsigned char*)p)[i] != 0;
    else if (kind == 0) m = ((const int*)p)[i] != 0;
    else                m = ((const float*)p)[i] != 0.0f;
    g_maskval[i] = m ? -1e30f : 0.0f;
}

// ---------------- fp32 -> bf16 hi/lo split ---------------------------------
__global__ void split_bf16_kernel(const float* __restrict__ src,
                                  unsigned short* __restrict__ hi,
                                  unsigned short* __restrict__ lo, int n4) {
    int i = blockIdx.x * blockDim.x + threadIdx.x;
    if (i >= n4) return;
    float4 v = ((const float4*)src)[i];
    float vv[4] = {v.x, v.y, v.z, v.w};
    unsigned short h[4], l[4];
#pragma unroll
    for (int j = 0; j < 4; j++) {
        __nv_bfloat16 bh = __float2bfloat16_rn(vv[j]);
        float r = vv[j] - __bfloat162float(bh);
        __nv_bfloat16 bl = __float2bfloat16_rn(r);
        h[j] = __bfloat16_as_ushort(bh);
        l[j] = __bfloat16_as_ushort(bl);
    }
    uint2 ph, pl;
    ph.x = (uint32_t)h[0] | ((uint32_t)h[1] << 16);
    ph.y = (uint32_t)h[2] | ((uint32_t)h[3] << 16);
    pl.x = (uint32_t)l[0] | ((uint32_t)l[1] << 16);
    pl.y = (uint32_t)l[2] | ((uint32_t)l[3] << 16);
    *(uint2*)(hi + 4 * (size_t)i) = ph;
    *(uint2*)(lo + 4 * (size_t)i) = pl;
}

// ---------------- split-bf16 mma.sync GEMM ----------------------------------
// C[4096,1024] = (A @ B^T + bias) * scale.  A [M,K] hi/lo bf16, B [N,K] hi/lo.
// CTA tile 128x128, K-chunk 32. 8 warps: 4 along M (32 rows), 2 along N (64 cols).
#define ASTR 40   // padded bf16 stride (conflict-free ldmatrix)

__global__ void __launch_bounds__(256, 1) gemm_mma_kernel(
    const unsigned short* __restrict__ Ah, const unsigned short* __restrict__ Al,
    const unsigned short* __restrict__ Bh, const unsigned short* __restrict__ Bl,
    const float* __restrict__ bias, float* __restrict__ C,
    float scale, int map_bhld)
{
    __shared__ __align__(16) unsigned short sAh[128 * ASTR], sAl[128 * ASTR];
    __shared__ __align__(16) unsigned short sBh[128 * ASTR], sBl[128 * ASTR];

    const int tid = threadIdx.x, wid = tid >> 5, lane = tid & 31;
    const int m0 = blockIdx.x * 128, n0 = blockIdx.y * 128;
    const int warp_m = (wid & 3) * 32;
    const int warp_n = (wid >> 2) * 64;

    const uint32_t sAh_b = smem_u32(sAh), sAl_b = smem_u32(sAl);
    const uint32_t sBh_b = smem_u32(sBh), sBl_b = smem_u32(sBl);

    // per-lane ldmatrix row/col selectors
    const int a_row = warp_m + (lane & 15);
    const int a_csel = (lane >> 4) << 3;          // 0 or 8
    const int b_row = warp_n + ((lane >> 4) << 3) + (lane & 7);
    const int b_csel = ((lane >> 3) & 1) << 3;    // 0 or 8

    float acc[2][8][4];
#pragma unroll
    for (int mb = 0; mb < 2; mb++)
#pragma unroll
        for (int nb = 0; nb < 8; nb++)
#pragma unroll
            for (int q = 0; q < 4; q++) acc[mb][nb][q] = 0.0f;

    const int ldr = tid >> 3, ldc = (tid & 7) << 2;   // 128 rows x 32 cols per buffer

    for (int kc = 0; kc < 32; kc++) {
        const int k0 = kc * 32;
        __syncthreads();
        {
            // each thread: 4 rows apart (256 threads -> 1024 uint2 loads)
#pragma unroll
            for (int rep = 0; rep < 4; rep++) {
                int r = ldr + rep * 32;
                size_t goA = (size_t)(m0 + r) * 1024 + k0 + ldc;
                size_t goB = (size_t)(n0 + r) * 1024 + k0 + ldc;
                int so = r * ASTR + ldc;
                *(uint2*)&sAh[so] = *(const uint2*)(Ah + goA);
                *(uint2*)&sAl[so] = *(const uint2*)(Al + goA);
                *(uint2*)&sBh[so] = *(const uint2*)(Bh + goB);
                *(uint2*)&sBl[so] = *(const uint2*)(Bl + goB);
            }
        }
        __syncthreads();

#pragma unroll
        for (int kk = 0; kk < 32; kk += 16) {
            uint32_t afh[2][4], afl[2][4];
#pragma unroll
            for (int mb = 0; mb < 2; mb++) {
                uint32_t off = (uint32_t)(((a_row + mb * 16) * ASTR + kk + a_csel) * 2);
                ldsm_x4(afh[mb], sAh_b + off);
                ldsm_x4(afl[mb], sAl_b + off);
            }
            uint32_t bfh[8][2], bfl[8][2];
#pragma unroll
            for (int nb2 = 0; nb2 < 4; nb2++) {
                uint32_t off = (uint32_t)(((b_row + nb2 * 16) * ASTR + kk + b_csel) * 2);
                uint32_t t[4];
                ldsm_x4(t, sBh_b + off);
                bfh[nb2 * 2][0] = t[0]; bfh[nb2 * 2][1] = t[1];
                bfh[nb2 * 2 + 1][0] = t[2]; bfh[nb2 * 2 + 1][1] = t[3];
                ldsm_x4(t, sBl_b + off);
                bfl[nb2 * 2][0] = t[0]; bfl[nb2 * 2][1] = t[1];
                bfl[nb2 * 2 + 1][0] = t[2]; bfl[nb2 * 2 + 1][1] = t[3];
            }
#pragma unroll
            for (int mb = 0; mb < 2; mb++)
#pragma unroll
                for (int nb = 0; nb < 8; nb++) {
                    mma_bf16(acc[mb][nb], afh[mb], bfh[nb]);
                    mma_bf16(acc[mb][nb], afh[mb], bfl[nb]);
                    mma_bf16(acc[mb][nb], afl[mb], bfh[nb]);
                }
        }
    }

    // epilogue: direct register -> gmem
    const int g = lane >> 2, tg = lane & 3;
#pragma unroll
    for (int mb = 0; mb < 2; mb++) {
#pragma unroll
        for (int nb = 0; nb < 8; nb++) {
            int n = n0 + warp_n + nb * 8 + tg * 2;
            float b0 = bias[n], b1 = bias[n + 1];
#pragma unroll
            for (int half = 0; half < 2; half++) {
                int m = m0 + warp_m + mb * 16 + g + half * 8;
                float2 v;
                v.x = (acc[mb][nb][half * 2 + 0] + b0) * scale;
                v.y = (acc[mb][nb][half * 2 + 1] + b1) * scale;
                if (map_bhld) {
                    int b = m >> 10, t = m & 1023, h = n >> 6, d = n & 63;
                    *(float2*)(C + (((size_t)(b * NH + h)) * TLEN + t) * HD + d) = v;
                } else {
                    *(float2*)(C + (size_t)m * 1024 + n) = v;
                }
            }
        }
    }
}

// ---------------- fused flash attention (unchanged from R1) ----------------
struct FlashSmem {
    float Q[64][65];
    float Kt[64][65];
    float V[64][65];
    float S[64][65];
    float maskv[64];
    float mrow[64];
    float lrow[64];
    float arow[64];
};

__global__ void flash_kernel(const float* __restrict__ attn_bias) {
    extern __shared__ char smraw[];
    FlashSmem* sm = (FlashSmem*)smraw;
    int tid = threadIdx.x;
    int t0 = blockIdx.x * 64;
    int h = blockIdx.y, b = blockIdx.z;
    int bh = b * NH + h;
    const float* qbase = g_q + (size_t)bh * TLEN * HD;
    const float* kbase = g_k + (size_t)bh * TLEN * HD;
    const float* vbase = g_v + (size_t)bh * TLEN * HD;
    const float* biasbase = attn_bias + (size_t)bh * TLEN * TLEN;
    int tx = tid & 15, ty = tid >> 4;

#pragma unroll
    for (int rep = 0; rep < 4; rep++) {
        int idx = rep * 256 + tid;
        int r = idx >> 4, c4 = (idx & 15) << 2;
        float4 q4 = *(const float4*)(qbase + (size_t)(t0 + r) * HD + c4);
        sm->Q[r][c4 + 0] = q4.x; sm->Q[r][c4 + 1] = q4.y;
        sm->Q[r][c4 + 2] = q4.z; sm->Q[r][c4 + 3] = q4.w;
    }
    if (tid < 64) { sm->mrow[tid] = -1e30f; sm->lrow[tid] = 0.0f; }

    float acc[4][4] = {};

    for (int s0 = 0; s0 < TLEN; s0 += 64) {
        __syncthreads();

#pragma unroll
        for (int rep = 0; rep < 4; rep++) {
            int idx = rep * 256 + tid;
            int r = idx >> 4, c4 = (idx & 15) << 2;
            float4 k4 = *(const float4*)(kbase + (size_t)(s0 + r) * HD + c4);
            sm->Kt[r][c4 + 0] = k4.x; sm->Kt[r][c4 + 1] = k4.y;
            sm->Kt[r][c4 + 2] = k4.z; sm->Kt[r][c4 + 3] = k4.w;
            float4 v4 = *(const float4*)(vbase + (size_t)(s0 + r) * HD + c4);
            sm->V[r][c4 + 0] = v4.x; sm->V[r][c4 + 1] = v4.y;
            sm->V[r][c4 + 2] = v4.z; sm->V[r][c4 + 3] = v4.w;
        }
        if (tid < 64) sm->maskv[tid] = g_maskval[b * TLEN + s0 + tid];
        __syncthreads();

        float sacc[4][4] = {};
#pragma unroll 8
        for (int d = 0; d < 64; d++) {
            float af[4], bf[4];
#pragma unroll
            for (int i = 0; i < 4; i++) af[i] = sm->Q[ty * 4 + i][d];
#pragma unroll
            for (int j = 0; j < 4; j++) bf[j] = sm->Kt[tx * 4 + j][d];
#pragma unroll
            for (int i = 0; i < 4; i++)
#pragma unroll
                for (int j = 0; j < 4; j++)
                    sacc[i][j] += af[i] * bf[j];
        }
#pragma unroll
        for (int i = 0; i < 4; i++) {
            int t = t0 + ty * 4 + i;
            float4 b4 = *(const float4*)(biasbase + (size_t)t * TLEN + s0 + tx * 4);
            sm->S[ty * 4 + i][tx * 4 + 0] = sacc[i][0] + b4.x + sm->maskv[tx * 4 + 0];
            sm->S[ty * 4 + i][tx * 4 + 1] = sacc[i][1] + b4.y + sm->maskv[tx * 4 + 1];
            sm->S[ty * 4 + i][tx * 4 + 2] = sacc[i][2] + b4.z + sm->maskv[tx * 4 + 2];
            sm->S[ty * 4 + i][tx * 4 + 3] = sacc[i][3] + b4.w + sm->maskv[tx * 4 + 3];
        }
        __syncthreads();

        if (tid < 64) {
            float m_old = sm->mrow[tid];
            float mx = m_old;
#pragma unroll 8
            for (int s = 0; s < 64; s++) mx = fmaxf(mx, sm->S[tid][s]);
            float alpha = __expf(m_old - mx);
            float sum = 0.0f;
#pragma unroll 8
            for (int s = 0; s < 64; s++) {
                float pv = __expf(sm->S[tid][s] - mx);
                sm->S[tid][s] = pv;
                sum += pv;
            }
            sm->lrow[tid] = sm->lrow[tid] * alpha + sum;
            sm->mrow[tid] = mx;
            sm->arow[tid] = alpha;
        }
        __syncthreads();

        float a[4];
#pragma unroll
        for (int i = 0; i < 4; i++) a[i] = sm->arow[ty * 4 + i];
#pragma unroll
        for (int i = 0; i < 4; i++)
#pragma unroll
            for (int j = 0; j < 4; j++)
                acc[i][j] *= a[i];
#pragma unroll 8
        for (int s = 0; s < 64; s++) {
            float pf[4], vf[4];
#pragma unroll
            for (int i = 0; i < 4; i++) pf[i] = sm->S[ty * 4 + i][s];
#pragma unroll
            for (int j = 0; j < 4; j++) vf[j] = sm->V[s][tx * 4 + j];
#pragma unroll
            for (int i = 0; i < 4; i++)
#pragma unroll
                for (int j = 0; j < 4; j++)
                    acc[i][j] += pf[i] * vf[j];
        }
    }

#pragma unroll
    for (int i = 0; i < 4; i++) {
        int row = ty * 4 + i;
        float linv = 1.0f / sm->lrow[row];
        float4 o4;
        o4.x = acc[i][0] * linv; o4.y = acc[i][1] * linv;
        o4.z = acc[i][2] * linv; o4.w = acc[i][3] * linv;
        size_t off = ((size_t)(b * TLEN + t0 + row)) * EE + h * HD + tx * 4;
        *(float4*)(g_ctx + off) = o4;
    }
}

// ---------------- launch ----------------------------------------------------
extern "C" void kernel_launch(void* const* d_in, const int* in_sizes, int n_in,
                              void* d_out, int out_size) {
    const float* query     = (const float*)d_in[0];
    const float* key       = (const float*)d_in[1];
    const float* value     = (const float*)d_in[2];
    const void*  mask      = d_in[3];
    const float* attn_bias = (const float*)d_in[4];
    const float* wq = (const float*)d_in[5];
    const float* bq = (const float*)d_in[6];
    const float* wk = (const float*)d_in[7];
    const float* bk = (const float*)d_in[8];
    const float* wv = (const float*)d_in[9];
    const float* bv = (const float*)d_in[10];
    const float* wo = (const float*)d_in[11];
    const float* bo = (const float*)d_in[12];
    float* out = (float*)d_out;

    void *pq, *pk, *pv, *pctx;
    cudaGetSymbolAddress(&pq, g_q);
    cudaGetSymbolAddress(&pk, g_k);
    cudaGetSymbolAddress(&pv, g_v);
    cudaGetSymbolAddress(&pctx, g_ctx);

    unsigned short *xqh, *xql, *xkh, *xkl, *xvh, *xvl, *cxh, *cxl;
    unsigned short *wqh, *wql, *wkh, *wkl, *wvh, *wvl, *woh, *wol;
    cudaGetSymbolAddress((void**)&xqh, g_xq_h); cudaGetSymbolAddress((void**)&xql, g_xq_l);
    cudaGetSymbolAddress((void**)&xkh, g_xk_h); cudaGetSymbolAddress((void**)&xkl, g_xk_l);
    cudaGetSymbolAddress((void**)&xvh, g_xv_h); cudaGetSymbolAddress((void**)&xvl, g_xv_l);
    cudaGetSymbolAddress((void**)&cxh, g_cx_h); cudaGetSymbolAddress((void**)&cxl, g_cx_l);
    cudaGetSymbolAddress((void**)&wqh, g_wq_h); cudaGetSymbolAddress((void**)&wql, g_wq_l);
    cudaGetSymbolAddress((void**)&wkh, g_wk_h); cudaGetSymbolAddress((void**)&wkl, g_wk_l);
    cudaGetSymbolAddress((void**)&wvh, g_wv_h); cudaGetSymbolAddress((void**)&wvl, g_wv_l);
    cudaGetSymbolAddress((void**)&woh, g_wo_h); cudaGetSymbolAddress((void**)&wol, g_wo_l);

    detect_mask_kernel<<<1, 256>>>((const unsigned char*)mask);
    expand_mask_kernel<<<(BB * TLEN + 255) / 256, 256>>>(mask);

    int act4 = ACT_ELEMS / 4, w4 = W_ELEMS / 4;
    split_bf16_kernel<<<(act4 + 255) / 256, 256>>>(query, xqh, xql, act4);
    split_bf16_kernel<<<(act4 + 255) / 256, 256>>>(key,   xkh, xkl, act4);
    split_bf16_kernel<<<(act4 + 255) / 256, 256>>>(value, xvh, xvl, act4);
    split_bf16_kernel<<<(w4 + 255) / 256, 256>>>(wq, wqh, wql, w4);
    split_bf16_kernel<<<(w4 + 255) / 256, 256>>>(wk, wkh, wkl, w4);
    split_bf16_kernel<<<(w4 + 255) / 256, 256>>>(wv, wvh, wvl, w4);
    split_bf16_kernel<<<(w4 + 255) / 256, 256>>>(wo, woh, wol, w4);

    dim3 gg(32, 8);  // 4096/128 x 1024/128
    gemm_mma_kernel<<<gg, 256>>>(xqh, xql, wqh, wql, bq, (float*)pq, SCALING, 1);
    gemm_mma_kernel<<<gg, 256>>>(xkh, xkl, wkh, wkl, bk, (float*)pk, 1.0f, 1);
    gemm_mma_kernel<<<gg, 256>>>(xvh, xvl, wvh, wvl, bv, (float*)pv, 1.0f, 1);

    cudaFuncSetAttribute(flash_kernel, cudaFuncAttributeMaxDynamicSharedMemorySize,
                         (int)sizeof(FlashSmem));
    flash_kernel<<<dim3(16, 16, 4), 256, sizeof(FlashSmem)>>>(attn_bias);

    split_bf16_kernel<<<(act4 + 255) / 256, 256>>>((const float*)pctx, cxh, cxl, act4);
    gemm_mma_kernel<<<gg, 256>>>(cxh, cxl, woh, wol, bo, out, 1.0f, 0);
}

// round 4
// speedup vs baseline: 2.0382x; 1.3486x over previous
#include <cuda_runtime.h>
#include <cuda_bf16.h>
#include <cstdint>

#define BB   4
#define TLEN 1024
#define EE   1024
#define NH   16
#define HD   64
#define SCALING 0.125f   // 64^-0.5

// ---------------- scratch (static device arrays; no runtime allocation) ----
__device__ float g_q[(size_t)BB*NH*TLEN*HD];    // 16 MB  [B,H,T,D]
__device__ float g_k[(size_t)BB*NH*TLEN*HD];    // 16 MB
__device__ float g_v[(size_t)BB*NH*TLEN*HD];    // 16 MB
__device__ float g_ctx[(size_t)BB*TLEN*EE];     // 16 MB  [B,T,E]
__device__ float g_maskval[BB*TLEN];            // 0 or -1e30 additive mask
__device__ int   g_mask_kind;                   // 0=int32, 1=uint8, 2=float32

// bf16 hi/lo split buffers
#define ACT_ELEMS (4096*1024)
#define W_ELEMS   (1024*1024)
__device__ unsigned short g_xq_h[ACT_ELEMS], g_xq_l[ACT_ELEMS];
__device__ unsigned short g_xk_h[ACT_ELEMS], g_xk_l[ACT_ELEMS];
__device__ unsigned short g_xv_h[ACT_ELEMS], g_xv_l[ACT_ELEMS];
__device__ unsigned short g_cx_h[ACT_ELEMS], g_cx_l[ACT_ELEMS];
__device__ unsigned short g_wq_h[W_ELEMS], g_wq_l[W_ELEMS];
__device__ unsigned short g_wk_h[W_ELEMS], g_wk_l[W_ELEMS];
__device__ unsigned short g_wv_h[W_ELEMS], g_wv_l[W_ELEMS];
__device__ unsigned short g_wo_h[W_ELEMS], g_wo_l[W_ELEMS];

// ---------------- warp-mma helpers -----------------------------------------
__device__ __forceinline__ uint32_t smem_u32(const void* p) {
    uint32_t a;
    asm("{ .reg .u64 t; cvta.to.shared.u64 t, %1; cvt.u32.u64 %0, t; }"
        : "=r"(a) : "l"(p));
    return a;
}

__device__ __forceinline__ void ldsm_x4(uint32_t r[4], uint32_t addr) {
    asm volatile("ldmatrix.sync.aligned.m8n8.x4.shared.b16 {%0,%1,%2,%3}, [%4];"
        : "=r"(r[0]), "=r"(r[1]), "=r"(r[2]), "=r"(r[3]) : "r"(addr));
}

__device__ __forceinline__ void ldsm_x4_t(uint32_t r[4], uint32_t addr) {
    asm volatile("ldmatrix.sync.aligned.m8n8.x4.trans.shared.b16 {%0,%1,%2,%3}, [%4];"
        : "=r"(r[0]), "=r"(r[1]), "=r"(r[2]), "=r"(r[3]) : "r"(addr));
}

__device__ __forceinline__ void mma_bf16(float c[4], const uint32_t a[4],
                                         const uint32_t b[2]) {
    asm volatile(
        "mma.sync.aligned.m16n8k16.row.col.f32.bf16.bf16.f32 "
        "{%0,%1,%2,%3}, {%4,%5,%6,%7}, {%8,%9}, {%0,%1,%2,%3};"
        : "+f"(c[0]), "+f"(c[1]), "+f"(c[2]), "+f"(c[3])
        : "r"(a[0]), "r"(a[1]), "r"(a[2]), "r"(a[3]), "r"(b[0]), "r"(b[1]));
}

// pack two fp32 -> bf16x2 (lo in bits 0-15, hi in bits 16-31)
__device__ __forceinline__ uint32_t pack_bf16x2(float lo, float hi) {
    uint32_t r;
    asm("cvt.rn.bf16x2.f32 %0, %1, %2;" : "=r"(r) : "f"(hi), "f"(lo));
    return r;
}

__device__ __forceinline__ float bf16_round(float x) {
    return __bfloat162float(__float2bfloat16_rn(x));
}

// ---------------- mask dtype sniffing --------------------------------------
__global__ void detect_mask_kernel(const unsigned char* __restrict__ p) {
    __shared__ int c0s, c1s;
    if (threadIdx.x == 0) { c0s = 0; c1s = 0; }
    __syncthreads();
    int c0 = 0, c1 = 0;
    for (int i = threadIdx.x; i < 1024; i += blockDim.x) {
        if (p[4 * i + 1]) c1++;
        if (p[4 * i + 0]) c0++;
    }
    if (c0) atomicAdd(&c0s, c0);
    if (c1) atomicAdd(&c1s, c1);
    __syncthreads();
    if (threadIdx.x == 0) g_mask_kind = c1s ? 1 : (c0s ? 0 : 2);
}

__global__ void expand_mask_kernel(const void* __restrict__ p) {
    int i = blockIdx.x * blockDim.x + threadIdx.x;
    if (i >= BB * TLEN) return;
    int kind = g_mask_kind;
    bool m;
    if (kind == 1)      m = ((const unsigned char*)p)[i] != 0;
    else if (kind == 0) m = ((const int*)p)[i] != 0;
    else                m = ((const float*)p)[i] != 0.0f;
    g_maskval[i] = m ? -1e30f : 0.0f;
}

// ---------------- fp32 -> bf16 hi/lo split ---------------------------------
__global__ void split_bf16_kernel(const float* __restrict__ src,
                                  unsigned short* __restrict__ hi,
                                  unsigned short* __restrict__ lo, int n4) {
    int i = blockIdx.x * blockDim.x + threadIdx.x;
    if (i >= n4) return;
    float4 v = ((const float4*)src)[i];
    float vv[4] = {v.x, v.y, v.z, v.w};
    unsigned short h[4], l[4];
#pragma unroll
    for (int j = 0; j < 4; j++) {
        __nv_bfloat16 bh = __float2bfloat16_rn(vv[j]);
        float r = vv[j] - __bfloat162float(bh);
        __nv_bfloat16 bl = __float2bfloat16_rn(r);
        h[j] = __bfloat16_as_ushort(bh);
        l[j] = __bfloat16_as_ushort(bl);
    }
    uint2 ph, pl;
    ph.x = (uint32_t)h[0] | ((uint32_t)h[1] << 16);
    ph.y = (uint32_t)h[2] | ((uint32_t)h[3] << 16);
    pl.x = (uint32_t)l[0] | ((uint32_t)l[1] << 16);
    pl.y = (uint32_t)l[2] | ((uint32_t)l[3] << 16);
    *(uint2*)(hi + 4 * (size_t)i) = ph;
    *(uint2*)(lo + 4 * (size_t)i) = pl;
}

// ---------------- split-bf16 mma.sync GEMM (unchanged from R3) --------------
#define ASTR 40

__global__ void __launch_bounds__(256, 1) gemm_mma_kernel(
    const unsigned short* __restrict__ Ah, const unsigned short* __restrict__ Al,
    const unsigned short* __restrict__ Bh, const unsigned short* __restrict__ Bl,
    const float* __restrict__ bias, float* __restrict__ C,
    float scale, int map_bhld)
{
    __shared__ __align__(16) unsigned short sAh[128 * ASTR], sAl[128 * ASTR];
    __shared__ __align__(16) unsigned short sBh[128 * ASTR], sBl[128 * ASTR];

    const int tid = threadIdx.x, wid = tid >> 5, lane = tid & 31;
    const int m0 = blockIdx.x * 128, n0 = blockIdx.y * 128;
    const int warp_m = (wid & 3) * 32;
    const int warp_n = (wid >> 2) * 64;

    const uint32_t sAh_b = smem_u32(sAh), sAl_b = smem_u32(sAl);
    const uint32_t sBh_b = smem_u32(sBh), sBl_b = smem_u32(sBl);

    const int a_row = warp_m + (lane & 15);
    const int a_csel = (lane >> 4) << 3;
    const int b_row = warp_n + ((lane >> 4) << 3) + (lane & 7);
    const int b_csel = ((lane >> 3) & 1) << 3;

    float acc[2][8][4];
#pragma unroll
    for (int mb = 0; mb < 2; mb++)
#pragma unroll
        for (int nb = 0; nb < 8; nb++)
#pragma unroll
            for (int q = 0; q < 4; q++) acc[mb][nb][q] = 0.0f;

    const int ldr = tid >> 3, ldc = (tid & 7) << 2;

    for (int kc = 0; kc < 32; kc++) {
        const int k0 = kc * 32;
        __syncthreads();
#pragma unroll
        for (int rep = 0; rep < 4; rep++) {
            int r = ldr + rep * 32;
            size_t goA = (size_t)(m0 + r) * 1024 + k0 + ldc;
            size_t goB = (size_t)(n0 + r) * 1024 + k0 + ldc;
            int so = r * ASTR + ldc;
            *(uint2*)&sAh[so] = *(const uint2*)(Ah + goA);
            *(uint2*)&sAl[so] = *(const uint2*)(Al + goA);
            *(uint2*)&sBh[so] = *(const uint2*)(Bh + goB);
            *(uint2*)&sBl[so] = *(const uint2*)(Bl + goB);
        }
        __syncthreads();

#pragma unroll
        for (int kk = 0; kk < 32; kk += 16) {
            uint32_t afh[2][4], afl[2][4];
#pragma unroll
            for (int mb = 0; mb < 2; mb++) {
                uint32_t off = (uint32_t)(((a_row + mb * 16) * ASTR + kk + a_csel) * 2);
                ldsm_x4(afh[mb], sAh_b + off);
                ldsm_x4(afl[mb], sAl_b + off);
            }
            uint32_t bfh[8][2], bfl[8][2];
#pragma unroll
            for (int nb2 = 0; nb2 < 4; nb2++) {
                uint32_t off = (uint32_t)(((b_row + nb2 * 16) * ASTR + kk + b_csel) * 2);
                uint32_t t[4];
                ldsm_x4(t, sBh_b + off);
                bfh[nb2 * 2][0] = t[0]; bfh[nb2 * 2][1] = t[1];
                bfh[nb2 * 2 + 1][0] = t[2]; bfh[nb2 * 2 + 1][1] = t[3];
                ldsm_x4(t, sBl_b + off);
                bfl[nb2 * 2][0] = t[0]; bfl[nb2 * 2][1] = t[1];
                bfl[nb2 * 2 + 1][0] = t[2]; bfl[nb2 * 2 + 1][1] = t[3];
            }
#pragma unroll
            for (int mb = 0; mb < 2; mb++)
#pragma unroll
                for (int nb = 0; nb < 8; nb++) {
                    mma_bf16(acc[mb][nb], afh[mb], bfh[nb]);
                    mma_bf16(acc[mb][nb], afh[mb], bfl[nb]);
                    mma_bf16(acc[mb][nb], afl[mb], bfh[nb]);
                }
        }
    }

    const int g = lane >> 2, tg = lane & 3;
#pragma unroll
    for (int mb = 0; mb < 2; mb++) {
#pragma unroll
        for (int nb = 0; nb < 8; nb++) {
            int n = n0 + warp_n + nb * 8 + tg * 2;
            float b0 = bias[n], b1 = bias[n + 1];
#pragma unroll
            for (int half = 0; half < 2; half++) {
                int m = m0 + warp_m + mb * 16 + g + half * 8;
                float2 v;
                v.x = (acc[mb][nb][half * 2 + 0] + b0) * scale;
                v.y = (acc[mb][nb][half * 2 + 1] + b1) * scale;
                if (map_bhld) {
                    int b = m >> 10, t = m & 1023, h = n >> 6, d = n & 63;
                    *(float2*)(C + (((size_t)(b * NH + h)) * TLEN + t) * HD + d) = v;
                } else {
                    *(float2*)(C + (size_t)m * 1024 + n) = v;
                }
            }
        }
    }
}

// ---------------- tensor-core flash attention -------------------------------
// CTA: 128 threads (4 warps), 64 query rows of one (b,h). Grid (16,16,4).
// smem (dynamic, bytes): Qh 0, Ql 9216, Kh 18432, Kl 27648, Vh 36864,
//                        Vl 46080, mask 55296..55552
#define FPAD 72
#define FBUF (64 * FPAD * 2)   // 9216 bytes per bf16 buffer

__global__ void __launch_bounds__(128) flash_mma_kernel(
    const float* __restrict__ attn_bias)
{
    extern __shared__ char sm[];
    unsigned short* sQh = (unsigned short*)(sm);
    unsigned short* sQl = (unsigned short*)(sm + FBUF);
    unsigned short* sKh = (unsigned short*)(sm + 2 * FBUF);
    unsigned short* sKl = (unsigned short*)(sm + 3 * FBUF);
    unsigned short* sVh = (unsigned short*)(sm + 4 * FBUF);
    unsigned short* sVl = (unsigned short*)(sm + 5 * FBUF);
    float* smask = (float*)(sm + 6 * FBUF);

    const int tid = threadIdx.x, wid = tid >> 5, lane = tid & 31;
    const int t0 = blockIdx.x * 64, h = blockIdx.y, b = blockIdx.z;
    const int bh = b * NH + h;
    const float* qbase = g_q + (size_t)bh * TLEN * HD;
    const float* kbase = g_k + (size_t)bh * TLEN * HD;
    const float* vbase = g_v + (size_t)bh * TLEN * HD;
    const float* biasbase = attn_bias + (size_t)bh * TLEN * TLEN;

    const int warp_m = wid * 16;
    const int g = lane >> 2, tq = lane & 3;

    const uint32_t sQh_b = smem_u32(sQh), sQl_b = smem_u32(sQl);
    const uint32_t sKh_b = smem_u32(sKh), sKl_b = smem_u32(sKl);
    const uint32_t sVh_b = smem_u32(sVh), sVl_b = smem_u32(sVl);

    // ---- fill Q tile (split fp32 -> bf16 hi/lo) ----
    for (int i = tid; i < 1024; i += 128) {
        int r = i >> 4, c4 = (i & 15) << 2;
        float4 q = *(const float4*)(qbase + (size_t)(t0 + r) * HD + c4);
        float vv[4] = {q.x, q.y, q.z, q.w};
        unsigned short hh[4], ll[4];
#pragma unroll
        for (int j = 0; j < 4; j++) {
            __nv_bfloat16 bhv = __float2bfloat16_rn(vv[j]);
            hh[j] = __bfloat16_as_ushort(bhv);
            ll[j] = __bfloat16_as_ushort(__float2bfloat16_rn(vv[j] - __bfloat162float(bhv)));
        }
        uint2 ph, pl;
        ph.x = (uint32_t)hh[0] | ((uint32_t)hh[1] << 16);
        ph.y = (uint32_t)hh[2] | ((uint32_t)hh[3] << 16);
        pl.x = (uint32_t)ll[0] | ((uint32_t)ll[1] << 16);
        pl.y = (uint32_t)ll[2] | ((uint32_t)ll[3] << 16);
        *(uint2*)&sQh[r * FPAD + c4] = ph;
        *(uint2*)&sQl[r * FPAD + c4] = pl;
    }
    __syncthreads();

    // ---- preload Q fragments (4 ksteps over d=64) ----
    const int a_row = warp_m + (lane & 15);
    const int a_csel = (lane >> 4) << 3;
    uint32_t qh[4][4], ql[4][4];
#pragma unroll
    for (int kk = 0; kk < 4; kk++) {
        uint32_t off = (uint32_t)((a_row * FPAD + kk * 16 + a_csel) * 2);
        ldsm_x4(qh[kk], sQh_b + off);
        ldsm_x4(ql[kk], sQl_b + off);
    }

    float accO[8][4];
#pragma unroll
    for (int nb = 0; nb < 8; nb++)
#pragma unroll
        for (int q = 0; q < 4; q++) accO[nb][q] = 0.0f;
    float mrow0 = -1e30f, mrow1 = -1e30f, lrow0 = 0.0f, lrow1 = 0.0f;

    const int b_rowbase = ((lane >> 4) << 3) + (lane & 7);
    const int b_csel = ((lane >> 3) & 1) << 3;
    // trans-ldmatrix address components for V
    const int v_key = (((lane >> 3) & 1) << 3) + (lane & 7);
    const int v_dof = (lane >> 4) << 3;

    for (int s0 = 0; s0 < TLEN; s0 += 64) {
        __syncthreads();
        // ---- fill K/V tiles (split) + mask slice ----
        for (int i = tid; i < 1024; i += 128) {
            int r = i >> 4, c4 = (i & 15) << 2;
            float4 kv = *(const float4*)(kbase + (size_t)(s0 + r) * HD + c4);
            float4 vv4 = *(const float4*)(vbase + (size_t)(s0 + r) * HD + c4);
            float kk4[4] = {kv.x, kv.y, kv.z, kv.w};
            float vvv[4] = {vv4.x, vv4.y, vv4.z, vv4.w};
            unsigned short kh[4], kl[4], vh[4], vl[4];
#pragma unroll
            for (int j = 0; j < 4; j++) {
                __nv_bfloat16 t1 = __float2bfloat16_rn(kk4[j]);
                kh[j] = __bfloat16_as_ushort(t1);
                kl[j] = __bfloat16_as_ushort(__float2bfloat16_rn(kk4[j] - __bfloat162float(t1)));
                __nv_bfloat16 t2 = __float2bfloat16_rn(vvv[j]);
                vh[j] = __bfloat16_as_ushort(t2);
                vl[j] = __bfloat16_as_ushort(__float2bfloat16_rn(vvv[j] - __bfloat162float(t2)));
            }
            uint2 u;
            u.x = (uint32_t)kh[0] | ((uint32_t)kh[1] << 16);
            u.y = (uint32_t)kh[2] | ((uint32_t)kh[3] << 16);
            *(uint2*)&sKh[r * FPAD + c4] = u;
            u.x = (uint32_t)kl[0] | ((uint32_t)kl[1] << 16);
            u.y = (uint32_t)kl[2] | ((uint32_t)kl[3] << 16);
            *(uint2*)&sKl[r * FPAD + c4] = u;
            u.x = (uint32_t)vh[0] | ((uint32_t)vh[1] << 16);
            u.y = (uint32_t)vh[2] | ((uint32_t)vh[3] << 16);
            *(uint2*)&sVh[r * FPAD + c4] = u;
            u.x = (uint32_t)vl[0] | ((uint32_t)vl[1] << 16);
            u.y = (uint32_t)vl[2] | ((uint32_t)vl[3] << 16);
            *(uint2*)&sVl[r * FPAD + c4] = u;
        }
        if (tid < 64) smask[tid] = g_maskval[b * TLEN + s0 + tid];
        __syncthreads();

        // ---- S = Qh*Kh + Qh*Kl + Ql*Kh ----
        float accS[8][4];
#pragma unroll
        for (int nb = 0; nb < 8; nb++)
#pragma unroll
            for (int q = 0; q < 4; q++) accS[nb][q] = 0.0f;

#pragma unroll
        for (int kk = 0; kk < 4; kk++) {
#pragma unroll
            for (int nb2 = 0; nb2 < 4; nb2++) {
                uint32_t off = (uint32_t)(((b_rowbase + nb2 * 16) * FPAD + kk * 16 + b_csel) * 2);
                uint32_t th[4], tl[4];
                ldsm_x4(th, sKh_b + off);
                ldsm_x4(tl, sKl_b + off);
                uint32_t bh0[2] = {th[0], th[1]}, bh1[2] = {th[2], th[3]};
                uint32_t bl0[2] = {tl[0], tl[1]}, bl1[2] = {tl[2], tl[3]};
                mma_bf16(accS[nb2 * 2],     qh[kk], bh0);
                mma_bf16(accS[nb2 * 2 + 1], qh[kk], bh1);
                mma_bf16(accS[nb2 * 2],     qh[kk], bl0);
                mma_bf16(accS[nb2 * 2 + 1], qh[kk], bl1);
                mma_bf16(accS[nb2 * 2],     ql[kk], bh0);
                mma_bf16(accS[nb2 * 2 + 1], ql[kk], bh1);
            }
        }

        // ---- add bias + mask ----
        const int row0 = t0 + warp_m + g;
        const int row1 = row0 + 8;
#pragma unroll
        for (int nb = 0; nb < 8; nb++) {
            int col = s0 + nb * 8 + tq * 2;
            float2 bv0 = *(const float2*)(biasbase + (size_t)row0 * TLEN + col);
            float2 bv1 = *(const float2*)(biasbase + (size_t)row1 * TLEN + col);
            float mk0 = smask[nb * 8 + tq * 2];
            float mk1 = smask[nb * 8 + tq * 2 + 1];
            accS[nb][0] += bv0.x + mk0;
            accS[nb][1] += bv0.y + mk1;
            accS[nb][2] += bv1.x + mk0;
            accS[nb][3] += bv1.y + mk1;
        }

        // ---- online softmax (quad reductions) ----
        float mx0 = mrow0, mx1 = mrow1;
#pragma unroll
        for (int nb = 0; nb < 8; nb++) {
            mx0 = fmaxf(mx0, fmaxf(accS[nb][0], accS[nb][1]));
            mx1 = fmaxf(mx1, fmaxf(accS[nb][2], accS[nb][3]));
        }
        mx0 = fmaxf(mx0, __shfl_xor_sync(0xFFFFFFFF, mx0, 1));
        mx0 = fmaxf(mx0, __shfl_xor_sync(0xFFFFFFFF, mx0, 2));
        mx1 = fmaxf(mx1, __shfl_xor_sync(0xFFFFFFFF, mx1, 1));
        mx1 = fmaxf(mx1, __shfl_xor_sync(0xFFFFFFFF, mx1, 2));
        float al0 = __expf(mrow0 - mx0), al1 = __expf(mrow1 - mx1);
        mrow0 = mx0; mrow1 = mx1;

        float sum0 = 0.0f, sum1 = 0.0f;
#pragma unroll
        for (int nb = 0; nb < 8; nb++) {
            accS[nb][0] = __expf(accS[nb][0] - mx0);
            accS[nb][1] = __expf(accS[nb][1] - mx0);
            accS[nb][2] = __expf(accS[nb][2] - mx1);
            accS[nb][3] = __expf(accS[nb][3] - mx1);
            sum0 += accS[nb][0] + accS[nb][1];
            sum1 += accS[nb][2] + accS[nb][3];
        }
        sum0 += __shfl_xor_sync(0xFFFFFFFF, sum0, 1);
        sum0 += __shfl_xor_sync(0xFFFFFFFF, sum0, 2);
        sum1 += __shfl_xor_sync(0xFFFFFFFF, sum1, 1);
        sum1 += __shfl_xor_sync(0xFFFFFFFF, sum1, 2);
        lrow0 = lrow0 * al0 + sum0;
        lrow1 = lrow1 * al1 + sum1;

        // rescale O
#pragma unroll
        for (int nb = 0; nb < 8; nb++) {
            accO[nb][0] *= al0; accO[nb][1] *= al0;
            accO[nb][2] *= al1; accO[nb][3] *= al1;
        }

        // ---- PV: O += (Ph + Pl) @ (Vh + Vl) (3 terms) ----
#pragma unroll
        for (int ks = 0; ks < 4; ks++) {
            // A fragments from accS[2ks], accS[2ks+1]
            float p00 = accS[2 * ks][0],     p01 = accS[2 * ks][1];
            float p02 = accS[2 * ks][2],     p03 = accS[2 * ks][3];
            float p10 = accS[2 * ks + 1][0], p11 = accS[2 * ks + 1][1];
            float p12 = accS[2 * ks + 1][2], p13 = accS[2 * ks + 1][3];
            float h00 = bf16_round(p00), h01 = bf16_round(p01);
            float h02 = bf16_round(p02), h03 = bf16_round(p03);
            float h10 = bf16_round(p10), h11 = bf16_round(p11);
            float h12 = bf16_round(p12), h13 = bf16_round(p13);
            uint32_t ph[4], pl[4];
            ph[0] = pack_bf16x2(h00, h01);
            ph[1] = pack_bf16x2(h02, h03);
            ph[2] = pack_bf16x2(h10, h11);
            ph[3] = pack_bf16x2(h12, h13);
            pl[0] = pack_bf16x2(p00 - h00, p01 - h01);
            pl[1] = pack_bf16x2(p02 - h02, p03 - h03);
            pl[2] = pack_bf16x2(p10 - h10, p11 - h11);
            pl[3] = pack_bf16x2(p12 - h12, p13 - h13);

#pragma unroll
            for (int db2 = 0; db2 < 4; db2++) {
                uint32_t addr = (uint32_t)(((ks * 16 + v_key) * FPAD
                                            + db2 * 16 + v_dof) * 2);
                uint32_t tvh[4], tvl[4];
                ldsm_x4_t(tvh, sVh_b + addr);
                ldsm_x4_t(tvl, sVl_b + addr);
                uint32_t bh0[2] = {tvh[0], tvh[1]}, bh1[2] = {tvh[2], tvh[3]};
                uint32_t bl0[2] = {tvl[0], tvl[1]}, bl1[2] = {tvl[2], tvl[3]};
                mma_bf16(accO[db2 * 2],     ph, bh0);
                mma_bf16(accO[db2 * 2 + 1], ph, bh1);
                mma_bf16(accO[db2 * 2],     ph, bl0);
                mma_bf16(accO[db2 * 2 + 1], ph, bl1);
                mma_bf16(accO[db2 * 2],     pl, bh0);
                mma_bf16(accO[db2 * 2 + 1], pl, bh1);
            }
        }
    }

    // ---- epilogue: O /= l, write [B,T,E] ----
    float li0 = 1.0f / lrow0, li1 = 1.0f / lrow1;
    const int row0 = t0 + warp_m + g;
    const int row1 = row0 + 8;
#pragma unroll
    for (int nb = 0; nb < 8; nb++) {
        int d = h * HD + nb * 8 + tq * 2;
        float2 o0, o1;
        o0.x = accO[nb][0] * li0; o0.y = accO[nb][1] * li0;
        o1.x = accO[nb][2] * li1; o1.y = accO[nb][3] * li1;
        *(float2*)(g_ctx + ((size_t)(b * TLEN + row0)) * EE + d) = o0;
        *(float2*)(g_ctx + ((size_t)(b * TLEN + row1)) * EE + d) = o1;
    }
}

// ---------------- launch ----------------------------------------------------
extern "C" void kernel_launch(void* const* d_in, const int* in_sizes, int n_in,
                              void* d_out, int out_size) {
    const float* query     = (const float*)d_in[0];
    const float* key       = (const float*)d_in[1];
    const float* value     = (const float*)d_in[2];
    const void*  mask      = d_in[3];
    const float* attn_bias = (const float*)d_in[4];
    const float* wq = (const float*)d_in[5];
    const float* bq = (const float*)d_in[6];
    const float* wk = (const float*)d_in[7];
    const float* bk = (const float*)d_in[8];
    const float* wv = (const float*)d_in[9];
    const float* bv = (const float*)d_in[10];
    const float* wo = (const float*)d_in[11];
    const float* bo = (const float*)d_in[12];
    float* out = (float*)d_out;

    void *pq, *pk, *pv, *pctx;
    cudaGetSymbolAddress(&pq, g_q);
    cudaGetSymbolAddress(&pk, g_k);
    cudaGetSymbolAddress(&pv, g_v);
    cudaGetSymbolAddress(&pctx, g_ctx);

    unsigned short *xqh, *xql, *xkh, *xkl, *xvh, *xvl, *cxh, *cxl;
    unsigned short *wqh, *wql, *wkh, *wkl, *wvh, *wvl, *woh, *wol;
    cudaGetSymbolAddress((void**)&xqh, g_xq_h); cudaGetSymbolAddress((void**)&xql, g_xq_l);
    cudaGetSymbolAddress((void**)&xkh, g_xk_h); cudaGetSymbolAddress((void**)&xkl, g_xk_l);
    cudaGetSymbolAddress((void**)&xvh, g_xv_h); cudaGetSymbolAddress((void**)&xvl, g_xv_l);
    cudaGetSymbolAddress((void**)&cxh, g_cx_h); cudaGetSymbolAddress((void**)&cxl, g_cx_l);
    cudaGetSymbolAddress((void**)&wqh, g_wq_h); cudaGetSymbolAddress((void**)&wql, g_wq_l);
    cudaGetSymbolAddress((void**)&wkh, g_wk_h); cudaGetSymbolAddress((void**)&wkl, g_wk_l);
    cudaGetSymbolAddress((void**)&wvh, g_wv_h); cudaGetSymbolAddress((void**)&wvl, g_wv_l);
    cudaGetSymbolAddress((void**)&woh, g_wo_h); cudaGetSymbolAddress((void**)&wol, g_wo_l);

    detect_mask_kernel<<<1, 256>>>((const unsigned char*)mask);
    expand_mask_kernel<<<(BB * TLEN + 255) / 256, 256>>>(mask);

    int act4 = ACT_ELEMS / 4, w4 = W_ELEMS / 4;
    split_bf16_kernel<<<(act4 + 255) / 256, 256>>>(query, xqh, xql, act4);
    split_bf16_kernel<<<(act4 + 255) / 256, 256>>>(key,   xkh, xkl, act4);
    split_bf16_kernel<<<(act4 + 255) / 256, 256>>>(value, xvh, xvl, act4);
    split_bf16_kernel<<<(w4 + 255) / 256, 256>>>(wq, wqh, wql, w4);
    split_bf16_kernel<<<(w4 + 255) / 256, 256>>>(wk, wkh, wkl, w4);
    split_bf16_kernel<<<(w4 + 255) / 256, 256>>>(wv, wvh, wvl, w4);
    split_bf16_kernel<<<(w4 + 255) / 256, 256>>>(wo, woh, wol, w4);

    dim3 gg(32, 8);
    gemm_mma_kernel<<<gg, 256>>>(xqh, xql, wqh, wql, bq, (float*)pq, SCALING, 1);
    gemm_mma_kernel<<<gg, 256>>>(xkh, xkl, wkh, wkl, bk, (float*)pk, 1.0f, 1);
    gemm_mma_kernel<<<gg, 256>>>(xvh, xvl, wvh, wvl, bv, (float*)pv, 1.0f, 1);

    const int flash_smem = 6 * FBUF + 64 * (int)sizeof(float);
    cudaFuncSetAttribute(flash_mma_kernel,
                         cudaFuncAttributeMaxDynamicSharedMemorySize, flash_smem);
    flash_mma_kernel<<<dim3(16, 16, 4), 128, flash_smem>>>(attn_bias);

    split_bf16_kernel<<<(act4 + 255) / 256, 256>>>((const float*)pctx, cxh, cxl, act4);
    gemm_mma_kernel<<<gg, 256>>>(cxh, cxl, woh, wol, bo, out, 1.0f, 0);
}

// round 5
// speedup vs baseline: 2.3876x; 1.1714x over previous
#include <cuda_runtime.h>
#include <cuda_bf16.h>
#include <cstdint>

#define BB   4
#define TLEN 1024
#define EE   1024
#define NH   16
#define HD   64
#define SCALING 0.125f   // 64^-0.5

// ---------------- scratch (static device arrays; no runtime allocation) ----
__device__ float g_maskval[BB*TLEN];
__device__ int   g_mask_kind;

#define ACT_ELEMS (4096*1024)
#define W_ELEMS   (1024*1024)
// input splits (GEMM A operands)
__device__ unsigned short g_xq_h[ACT_ELEMS], g_xq_l[ACT_ELEMS];
__device__ unsigned short g_xk_h[ACT_ELEMS], g_xk_l[ACT_ELEMS];
__device__ unsigned short g_xv_h[ACT_ELEMS], g_xv_l[ACT_ELEMS];
__device__ unsigned short g_cx_h[ACT_ELEMS], g_cx_l[ACT_ELEMS];
// weight splits
__device__ unsigned short g_wq_h[W_ELEMS], g_wq_l[W_ELEMS];
__device__ unsigned short g_wk_h[W_ELEMS], g_wk_l[W_ELEMS];
__device__ unsigned short g_wv_h[W_ELEMS], g_wv_l[W_ELEMS];
__device__ unsigned short g_wo_h[W_ELEMS], g_wo_l[W_ELEMS];
// projected Q/K/V, pre-split bf16 hi/lo, [B,H,T,D]
__device__ unsigned short g_qh[ACT_ELEMS], g_ql[ACT_ELEMS];
__device__ unsigned short g_kh[ACT_ELEMS], g_kl[ACT_ELEMS];
__device__ unsigned short g_vh[ACT_ELEMS], g_vl[ACT_ELEMS];

// ---------------- warp-mma helpers -----------------------------------------
__device__ __forceinline__ uint32_t smem_u32(const void* p) {
    uint32_t a;
    asm("{ .reg .u64 t; cvta.to.shared.u64 t, %1; cvt.u32.u64 %0, t; }"
        : "=r"(a) : "l"(p));
    return a;
}

__device__ __forceinline__ void ldsm_x4(uint32_t r[4], uint32_t addr) {
    asm volatile("ldmatrix.sync.aligned.m8n8.x4.shared.b16 {%0,%1,%2,%3}, [%4];"
        : "=r"(r[0]), "=r"(r[1]), "=r"(r[2]), "=r"(r[3]) : "r"(addr));
}

__device__ __forceinline__ void ldsm_x4_t(uint32_t r[4], uint32_t addr) {
    asm volatile("ldmatrix.sync.aligned.m8n8.x4.trans.shared.b16 {%0,%1,%2,%3}, [%4];"
        : "=r"(r[0]), "=r"(r[1]), "=r"(r[2]), "=r"(r[3]) : "r"(addr));
}

__device__ __forceinline__ void mma_bf16(float c[4], const uint32_t a[4],
                                         const uint32_t b[2]) {
    asm volatile(
        "mma.sync.aligned.m16n8k16.row.col.f32.bf16.bf16.f32 "
        "{%0,%1,%2,%3}, {%4,%5,%6,%7}, {%8,%9}, {%0,%1,%2,%3};"
        : "+f"(c[0]), "+f"(c[1]), "+f"(c[2]), "+f"(c[3])
        : "r"(a[0]), "r"(a[1]), "r"(a[2]), "r"(a[3]), "r"(b[0]), "r"(b[1]));
}

__device__ __forceinline__ uint32_t pack_bf16x2(float lo, float hi) {
    uint32_t r;
    asm("cvt.rn.bf16x2.f32 %0, %1, %2;" : "=r"(r) : "f"(hi), "f"(lo));
    return r;
}

__device__ __forceinline__ float bf16_round(float x) {
    return __bfloat162float(__float2bfloat16_rn(x));
}

__device__ __forceinline__ void cp_async16(uint32_t smem_addr, const void* gptr) {
    asm volatile("cp.async.cg.shared.global [%0], [%1], 16;"
        :: "r"(smem_addr), "l"(gptr));
}
#define CP_COMMIT() asm volatile("cp.async.commit_group;" ::: "memory")
#define CP_WAIT(n)  asm volatile("cp.async.wait_group %0;" :: "n"(n) : "memory")

// ---------------- mask dtype sniffing --------------------------------------
__global__ void detect_mask_kernel(const unsigned char* __restrict__ p) {
    __shared__ int c0s, c1s;
    if (threadIdx.x == 0) { c0s = 0; c1s = 0; }
    __syncthreads();
    int c0 = 0, c1 = 0;
    for (int i = threadIdx.x; i < 1024; i += blockDim.x) {
        if (p[4 * i + 1]) c1++;
        if (p[4 * i + 0]) c0++;
    }
    if (c0) atomicAdd(&c0s, c0);
    if (c1) atomicAdd(&c1s, c1);
    __syncthreads();
    if (threadIdx.x == 0) g_mask_kind = c1s ? 1 : (c0s ? 0 : 2);
}

__global__ void expand_mask_kernel(const void* __restrict__ p) {
    int i = blockIdx.x * blockDim.x + threadIdx.x;
    if (i >= BB * TLEN) return;
    int kind = g_mask_kind;
    bool m;
    if (kind == 1)      m = ((const unsigned char*)p)[i] != 0;
    else if (kind == 0) m = ((const int*)p)[i] != 0;
    else                m = ((const float*)p)[i] != 0.0f;
    g_maskval[i] = m ? -1e30f : 0.0f;
}

// ---------------- fp32 -> bf16 hi/lo split ---------------------------------
__global__ void split_bf16_kernel(const float* __restrict__ src,
                                  unsigned short* __restrict__ hi,
                                  unsigned short* __restrict__ lo, int n4) {
    int i = blockIdx.x * blockDim.x + threadIdx.x;
    if (i >= n4) return;
    float4 v = ((const float4*)src)[i];
    float vv[4] = {v.x, v.y, v.z, v.w};
    unsigned short h[4], l[4];
#pragma unroll
    for (int j = 0; j < 4; j++) {
        __nv_bfloat16 bh = __float2bfloat16_rn(vv[j]);
        float r = vv[j] - __bfloat162float(bh);
        h[j] = __bfloat16_as_ushort(bh);
        l[j] = __bfloat16_as_ushort(__float2bfloat16_rn(r));
    }
    uint2 ph, pl;
    ph.x = (uint32_t)h[0] | ((uint32_t)h[1] << 16);
    ph.y = (uint32_t)h[2] | ((uint32_t)h[3] << 16);
    pl.x = (uint32_t)l[0] | ((uint32_t)l[1] << 16);
    pl.y = (uint32_t)l[2] | ((uint32_t)l[3] << 16);
    *(uint2*)(hi + 4 * (size_t)i) = ph;
    *(uint2*)(lo + 4 * (size_t)i) = pl;
}

// ---------------- cp.async double-buffered split-bf16 GEMM ------------------
// C = (A @ B^T + bias) * scale.  M=4096, N=1024, K=1024.
// CTA tile 128x128, k-chunk 16, 2 smem stages, 8 warps (4xM, 2xN).
// out_mode 0: fp32 [M,N] -> Cf ; out_mode 1: bf16 hi/lo split [B,H,T,D] -> Ch/Cl.
#define GSTR 24                      // smem stride (ushorts), conflict-free
#define GBUF (128 * GSTR * 2)        // 6144 B per operand buffer
#define GSTAGE (4 * GBUF)            // 24576 B per stage
#define GSMEM (2 * GSTAGE)           // 49152 B total

__global__ void __launch_bounds__(256, 2) gemm_cp_kernel(
    const unsigned short* __restrict__ Ah, const unsigned short* __restrict__ Al,
    const unsigned short* __restrict__ Bh, const unsigned short* __restrict__ Bl,
    const float* __restrict__ bias, float scale, int out_mode,
    float* __restrict__ Cf, unsigned short* __restrict__ Ch,
    unsigned short* __restrict__ Cl)
{
    extern __shared__ char smem[];
    const int tid = threadIdx.x, wid = tid >> 5, lane = tid & 31;
    const int m0 = blockIdx.x * 128, n0 = blockIdx.y * 128;
    const int warp_m = (wid & 3) * 32;
    const int warp_n = (wid >> 2) * 64;
    const uint32_t sbase = smem_u32(smem);

    // cp.async mapping: row = tid>>1 (0..127), half = tid&1
    const int cp_r = tid >> 1, cp_half = tid & 1;
    const uint32_t cp_soff = (uint32_t)(cp_r * (GSTR * 2) + cp_half * 16);
    const size_t cp_gA = (size_t)(m0 + cp_r) * 1024 + cp_half * 8;
    const size_t cp_gB = (size_t)(n0 + cp_r) * 1024 + cp_half * 8;

    const int a_row = warp_m + (lane & 15);
    const int a_csel = (lane >> 4) << 3;
    const int b_row = warp_n + ((lane >> 4) << 3) + (lane & 7);
    const int b_csel = ((lane >> 3) & 1) << 3;

    float acc[2][8][4];
#pragma unroll
    for (int mb = 0; mb < 2; mb++)
#pragma unroll
        for (int nb = 0; nb < 8; nb++)
#pragma unroll
            for (int q = 0; q < 4; q++) acc[mb][nb][q] = 0.0f;

    // issue stage for k-chunk kc into buffer kc&1
    auto issue = [&](int kc) {
        uint32_t st = sbase + (kc & 1) * GSTAGE;
        size_t kofs = (size_t)kc * 16;
        cp_async16(st + 0 * GBUF + cp_soff, Ah + cp_gA + kofs);
        cp_async16(st + 1 * GBUF + cp_soff, Al + cp_gA + kofs);
        cp_async16(st + 2 * GBUF + cp_soff, Bh + cp_gB + kofs);
        cp_async16(st + 3 * GBUF + cp_soff, Bl + cp_gB + kofs);
        CP_COMMIT();
    };

    issue(0);
    for (int kc = 0; kc < 64; kc++) {
        if (kc + 1 < 64) { issue(kc + 1); CP_WAIT(1); }
        else             { CP_WAIT(0); }
        __syncthreads();

        const uint32_t st = sbase + (kc & 1) * GSTAGE;
        uint32_t afh[2][4], afl[2][4];
#pragma unroll
        for (int mb = 0; mb < 2; mb++) {
            uint32_t off = (uint32_t)(((a_row + mb * 16) * GSTR + a_csel) * 2);
            ldsm_x4(afh[mb], st + 0 * GBUF + off);
            ldsm_x4(afl[mb], st + 1 * GBUF + off);
        }
#pragma unroll
        for (int nb2 = 0; nb2 < 4; nb2++) {
            uint32_t off = (uint32_t)(((b_row + nb2 * 16) * GSTR + b_csel) * 2);
            uint32_t th[4], tl[4];
            ldsm_x4(th, st + 2 * GBUF + off);
            ldsm_x4(tl, st + 3 * GBUF + off);
            uint32_t bh0[2] = {th[0], th[1]}, bh1[2] = {th[2], th[3]};
            uint32_t bl0[2] = {tl[0], tl[1]}, bl1[2] = {tl[2], tl[3]};
#pragma unroll
            for (int mb = 0; mb < 2; mb++) {
                mma_bf16(acc[mb][nb2 * 2],     afh[mb], bh0);
                mma_bf16(acc[mb][nb2 * 2 + 1], afh[mb], bh1);
                mma_bf16(acc[mb][nb2 * 2],     afh[mb], bl0);
                mma_bf16(acc[mb][nb2 * 2 + 1], afh[mb], bl1);
                mma_bf16(acc[mb][nb2 * 2],     afl[mb], bh0);
                mma_bf16(acc[mb][nb2 * 2 + 1], afl[mb], bh1);
            }
        }
        __syncthreads();
    }

    // epilogue
    const int g = lane >> 2, tg = lane & 3;
#pragma unroll
    for (int mb = 0; mb < 2; mb++) {
#pragma unroll
        for (int nb = 0; nb < 8; nb++) {
            int n = n0 + warp_n + nb * 8 + tg * 2;
            float b0 = bias[n], b1 = bias[n + 1];
#pragma unroll
            for (int half = 0; half < 2; half++) {
                int m = m0 + warp_m + mb * 16 + g + half * 8;
                float vx = (acc[mb][nb][half * 2 + 0] + b0) * scale;
                float vy = (acc[mb][nb][half * 2 + 1] + b1) * scale;
                if (out_mode == 1) {
                    int bb = m >> 10, t = m & 1023, hh = n >> 6, d = n & 63;
                    size_t off = (((size_t)(bb * NH + hh)) * TLEN + t) * HD + d;
                    float hx = bf16_round(vx), hy = bf16_round(vy);
                    *(uint32_t*)(Ch + off) = pack_bf16x2(hx, hy);
                    *(uint32_t*)(Cl + off) = pack_bf16x2(vx - hx, vy - hy);
                } else {
                    float2 v; v.x = vx; v.y = vy;
                    *(float2*)(Cf + (size_t)m * 1024 + n) = v;
                }
            }
        }
    }
}

// ---------------- tensor-core flash attention (pre-split inputs) ------------
#define FPAD 72
#define FBUF (64 * FPAD * 2)   // 9216 bytes per bf16 buffer

__global__ void __launch_bounds__(128) flash_mma_kernel(
    const float* __restrict__ attn_bias)
{
    extern __shared__ char sm[];
    unsigned short* sQh = (unsigned short*)(sm);
    unsigned short* sQl = (unsigned short*)(sm + FBUF);
    unsigned short* sKh = (unsigned short*)(sm + 2 * FBUF);
    unsigned short* sKl = (unsigned short*)(sm + 3 * FBUF);
    unsigned short* sVh = (unsigned short*)(sm + 4 * FBUF);
    unsigned short* sVl = (unsigned short*)(sm + 5 * FBUF);
    float* smask = (float*)(sm + 6 * FBUF);

    const int tid = threadIdx.x, wid = tid >> 5, lane = tid & 31;
    const int t0 = blockIdx.x * 64, h = blockIdx.y, b = blockIdx.z;
    const int bh = b * NH + h;
    const size_t base = (size_t)bh * TLEN * HD;
    const unsigned short *qh_g = g_qh + base, *ql_g = g_ql + base;
    const unsigned short *kh_g = g_kh + base, *kl_g = g_kl + base;
    const unsigned short *vh_g = g_vh + base, *vl_g = g_vl + base;
    const float* biasbase = attn_bias + (size_t)bh * TLEN * TLEN;

    const int warp_m = wid * 16;
    const int g = lane >> 2, tq = lane & 3;

    const uint32_t sQh_b = smem_u32(sQh), sQl_b = smem_u32(sQl);
    const uint32_t sKh_b = smem_u32(sKh), sKl_b = smem_u32(sKl);
    const uint32_t sVh_b = smem_u32(sVh), sVl_b = smem_u32(sVl);

    // ---- fill Q tile (plain copies of pre-split bf16) ----
    for (int i = tid; i < 1024; i += 128) {
        int r = i >> 4, c4 = (i & 15) << 2;
        size_t go = (size_t)(t0 + r) * HD + c4;
        *(uint2*)&sQh[r * FPAD + c4] = *(const uint2*)(qh_g + go);
        *(uint2*)&sQl[r * FPAD + c4] = *(const uint2*)(ql_g + go);
    }
    __syncthreads();

    const int a_row = warp_m + (lane & 15);
    const int a_csel = (lane >> 4) << 3;
    uint32_t qh[4][4], ql[4][4];
#pragma unroll
    for (int kk = 0; kk < 4; kk++) {
        uint32_t off = (uint32_t)((a_row * FPAD + kk * 16 + a_csel) * 2);
        ldsm_x4(qh[kk], sQh_b + off);
        ldsm_x4(ql[kk], sQl_b + off);
    }

    float accO[8][4];
#pragma unroll
    for (int nb = 0; nb < 8; nb++)
#pragma unroll
        for (int q = 0; q < 4; q++) accO[nb][q] = 0.0f;
    float mrow0 = -1e30f, mrow1 = -1e30f, lrow0 = 0.0f, lrow1 = 0.0f;

    const int b_rowbase = ((lane >> 4) << 3) + (lane & 7);
    const int b_csel = ((lane >> 3) & 1) << 3;
    const int v_key = (((lane >> 3) & 1) << 3) + (lane & 7);
    const int v_dof = (lane >> 4) << 3;

    for (int s0 = 0; s0 < TLEN; s0 += 64) {
        __syncthreads();
        for (int i = tid; i < 1024; i += 128) {
            int r = i >> 4, c4 = (i & 15) << 2;
            size_t go = (size_t)(s0 + r) * HD + c4;
            int so = r * FPAD + c4;
            *(uint2*)&sKh[so] = *(const uint2*)(kh_g + go);
            *(uint2*)&sKl[so] = *(const uint2*)(kl_g + go);
            *(uint2*)&sVh[so] = *(const uint2*)(vh_g + go);
            *(uint2*)&sVl[so] = *(const uint2*)(vl_g + go);
        }
        if (tid < 64) smask[tid] = g_maskval[b * TLEN + s0 + tid];
        __syncthreads();

        // ---- S = Qh*Kh + Qh*Kl + Ql*Kh ----
        float accS[8][4];
#pragma unroll
        for (int nb = 0; nb < 8; nb++)
#pragma unroll
            for (int q = 0; q < 4; q++) accS[nb][q] = 0.0f;

#pragma unroll
        for (int kk = 0; kk < 4; kk++) {
#pragma unroll
            for (int nb2 = 0; nb2 < 4; nb2++) {
                uint32_t off = (uint32_t)(((b_rowbase + nb2 * 16) * FPAD + kk * 16 + b_csel) * 2);
                uint32_t th[4], tl[4];
                ldsm_x4(th, sKh_b + off);
                ldsm_x4(tl, sKl_b + off);
                uint32_t bh0[2] = {th[0], th[1]}, bh1[2] = {th[2], th[3]};
                uint32_t bl0[2] = {tl[0], tl[1]}, bl1[2] = {tl[2], tl[3]};
                mma_bf16(accS[nb2 * 2],     qh[kk], bh0);
                mma_bf16(accS[nb2 * 2 + 1], qh[kk], bh1);
                mma_bf16(accS[nb2 * 2],     qh[kk], bl0);
                mma_bf16(accS[nb2 * 2 + 1], qh[kk], bl1);
                mma_bf16(accS[nb2 * 2],     ql[kk], bh0);
                mma_bf16(accS[nb2 * 2 + 1], ql[kk], bh1);
            }
        }

        // ---- add bias + mask ----
        const int row0 = t0 + warp_m + g;
        const int row1 = row0 + 8;
#pragma unroll
        for (int nb = 0; nb < 8; nb++) {
            int col = s0 + nb * 8 + tq * 2;
            float2 bv0 = *(const float2*)(biasbase + (size_t)row0 * TLEN + col);
            float2 bv1 = *(const float2*)(biasbase + (size_t)row1 * TLEN + col);
            float mk0 = smask[nb * 8 + tq * 2];
            float mk1 = smask[nb * 8 + tq * 2 + 1];
            accS[nb][0] += bv0.x + mk0;
            accS[nb][1] += bv0.y + mk1;
            accS[nb][2] += bv1.x + mk0;
            accS[nb][3] += bv1.y + mk1;
        }

        // ---- online softmax (quad reductions) ----
        float mx0 = mrow0, mx1 = mrow1;
#pragma unroll
        for (int nb = 0; nb < 8; nb++) {
            mx0 = fmaxf(mx0, fmaxf(accS[nb][0], accS[nb][1]));
            mx1 = fmaxf(mx1, fmaxf(accS[nb][2], accS[nb][3]));
        }
        mx0 = fmaxf(mx0, __shfl_xor_sync(0xFFFFFFFF, mx0, 1));
        mx0 = fmaxf(mx0, __shfl_xor_sync(0xFFFFFFFF, mx0, 2));
        mx1 = fmaxf(mx1, __shfl_xor_sync(0xFFFFFFFF, mx1, 1));
        mx1 = fmaxf(mx1, __shfl_xor_sync(0xFFFFFFFF, mx1, 2));
        float al0 = __expf(mrow0 - mx0), al1 = __expf(mrow1 - mx1);
        mrow0 = mx0; mrow1 = mx1;

        float sum0 = 0.0f, sum1 = 0.0f;
#pragma unroll
        for (int nb = 0; nb < 8; nb++) {
            accS[nb][0] = __expf(accS[nb][0] - mx0);
            accS[nb][1] = __expf(accS[nb][1] - mx0);
            accS[nb][2] = __expf(accS[nb][2] - mx1);
            accS[nb][3] = __expf(accS[nb][3] - mx1);
            sum0 += accS[nb][0] + accS[nb][1];
            sum1 += accS[nb][2] + accS[nb][3];
        }
        sum0 += __shfl_xor_sync(0xFFFFFFFF, sum0, 1);
        sum0 += __shfl_xor_sync(0xFFFFFFFF, sum0, 2);
        sum1 += __shfl_xor_sync(0xFFFFFFFF, sum1, 1);
        sum1 += __shfl_xor_sync(0xFFFFFFFF, sum1, 2);
        lrow0 = lrow0 * al0 + sum0;
        lrow1 = lrow1 * al1 + sum1;

#pragma unroll
        for (int nb = 0; nb < 8; nb++) {
            accO[nb][0] *= al0; accO[nb][1] *= al0;
            accO[nb][2] *= al1; accO[nb][3] *= al1;
        }

        // ---- PV: O += Ph*Vh + Ph*Vl + Pl*Vh ----
#pragma unroll
        for (int ks = 0; ks < 4; ks++) {
            float p00 = accS[2 * ks][0],     p01 = accS[2 * ks][1];
            float p02 = accS[2 * ks][2],     p03 = accS[2 * ks][3];
            float p10 = accS[2 * ks + 1][0], p11 = accS[2 * ks + 1][1];
            float p12 = accS[2 * ks + 1][2], p13 = accS[2 * ks + 1][3];
            float h00 = bf16_round(p00), h01 = bf16_round(p01);
            float h02 = bf16_round(p02), h03 = bf16_round(p03);
            float h10 = bf16_round(p10), h11 = bf16_round(p11);
            float h12 = bf16_round(p12), h13 = bf16_round(p13);
            uint32_t ph[4], pl[4];
            ph[0] = pack_bf16x2(h00, h01);
            ph[1] = pack_bf16x2(h02, h03);
            ph[2] = pack_bf16x2(h10, h11);
            ph[3] = pack_bf16x2(h12, h13);
            pl[0] = pack_bf16x2(p00 - h00, p01 - h01);
            pl[1] = pack_bf16x2(p02 - h02, p03 - h03);
            pl[2] = pack_bf16x2(p10 - h10, p11 - h11);
            pl[3] = pack_bf16x2(p12 - h12, p13 - h13);

#pragma unroll
            for (int db2 = 0; db2 < 4; db2++) {
                uint32_t addr = (uint32_t)(((ks * 16 + v_key) * FPAD
                                            + db2 * 16 + v_dof) * 2);
                uint32_t tvh[4], tvl[4];
                ldsm_x4_t(tvh, sVh_b + addr);
                ldsm_x4_t(tvl, sVl_b + addr);
                uint32_t bh0[2] = {tvh[0], tvh[1]}, bh1[2] = {tvh[2], tvh[3]};
                uint32_t bl0[2] = {tvl[0], tvl[1]}, bl1[2] = {tvl[2], tvl[3]};
                mma_bf16(accO[db2 * 2],     ph, bh0);
                mma_bf16(accO[db2 * 2 + 1], ph, bh1);
                mma_bf16(accO[db2 * 2],     ph, bl0);
                mma_bf16(accO[db2 * 2 + 1], ph, bl1);
                mma_bf16(accO[db2 * 2],     pl, bh0);
                mma_bf16(accO[db2 * 2 + 1], pl, bh1);
            }
        }
    }

    // ---- epilogue: O /= l, write pre-split ctx [B,T,E] ----
    float li0 = 1.0f / lrow0, li1 = 1.0f / lrow1;
    const int row0 = t0 + warp_m + g;
    const int row1 = row0 + 8;
#pragma unroll
    for (int nb = 0; nb < 8; nb++) {
        int d = h * HD + nb * 8 + tq * 2;
        float o0x = accO[nb][0] * li0, o0y = accO[nb][1] * li0;
        float o1x = accO[nb][2] * li1, o1y = accO[nb][3] * li1;
        size_t off0 = ((size_t)(b * TLEN + row0)) * EE + d;
        size_t off1 = ((size_t)(b * TLEN + row1)) * EE + d;
        float h0x = bf16_round(o0x), h0y = bf16_round(o0y);
        float h1x = bf16_round(o1x), h1y = bf16_round(o1y);
        *(uint32_t*)(g_cx_h + off0) = pack_bf16x2(h0x, h0y);
        *(uint32_t*)(g_cx_l + off0) = pack_bf16x2(o0x - h0x, o0y - h0y);
        *(uint32_t*)(g_cx_h + off1) = pack_bf16x2(h1x, h1y);
        *(uint32_t*)(g_cx_l + off1) = pack_bf16x2(o1x - h1x, o1y - h1y);
    }
}

// ---------------- launch ----------------------------------------------------
extern "C" void kernel_launch(void* const* d_in, const int* in_sizes, int n_in,
                              void* d_out, int out_size) {
    const float* query     = (const float*)d_in[0];
    const float* key       = (const float*)d_in[1];
    const float* value     = (const float*)d_in[2];
    const void*  mask      = d_in[3];
    const float* attn_bias = (const float*)d_in[4];
    const float* wq = (const float*)d_in[5];
    const float* bq = (const float*)d_in[6];
    const float* wk = (const float*)d_in[7];
    const float* bk = (const float*)d_in[8];
    const float* wv = (const float*)d_in[9];
    const float* bv = (const float*)d_in[10];
    const float* wo = (const float*)d_in[11];
    const float* bo = (const float*)d_in[12];
    float* out = (float*)d_out;

    unsigned short *xqh, *xql, *xkh, *xkl, *xvh, *xvl, *cxh, *cxl;
    unsigned short *wqh, *wql, *wkh, *wkl, *wvh, *wvl, *woh, *wol;
    unsigned short *qh, *ql, *kh, *kl, *vh, *vl;
    cudaGetSymbolAddress((void**)&xqh, g_xq_h); cudaGetSymbolAddress((void**)&xql, g_xq_l);
    cudaGetSymbolAddress((void**)&xkh, g_xk_h); cudaGetSymbolAddress((void**)&xkl, g_xk_l);
    cudaGetSymbolAddress((void**)&xvh, g_xv_h); cudaGetSymbolAddress((void**)&xvl, g_xv_l);
    cudaGetSymbolAddress((void**)&cxh, g_cx_h); cudaGetSymbolAddress((void**)&cxl, g_cx_l);
    cudaGetSymbolAddress((void**)&wqh, g_wq_h); cudaGetSymbolAddress((void**)&wql, g_wq_l);
    cudaGetSymbolAddress((void**)&wkh, g_wk_h); cudaGetSymbolAddress((void**)&wkl, g_wk_l);
    cudaGetSymbolAddress((void**)&wvh, g_wv_h); cudaGetSymbolAddress((void**)&wvl, g_wv_l);
    cudaGetSymbolAddress((void**)&woh, g_wo_h); cudaGetSymbolAddress((void**)&wol, g_wo_l);
    cudaGetSymbolAddress((void**)&qh, g_qh); cudaGetSymbolAddress((void**)&ql, g_ql);
    cudaGetSymbolAddress((void**)&kh, g_kh); cudaGetSymbolAddress((void**)&kl, g_kl);
    cudaGetSymbolAddress((void**)&vh, g_vh); cudaGetSymbolAddress((void**)&vl, g_vl);

    detect_mask_kernel<<<1, 256>>>((const unsigned char*)mask);
    expand_mask_kernel<<<(BB * TLEN + 255) / 256, 256>>>(mask);

    int act4 = ACT_ELEMS / 4, w4 = W_ELEMS / 4;
    split_bf16_kernel<<<(act4 + 255) / 256, 256>>>(query, xqh, xql, act4);
    split_bf16_kernel<<<(act4 + 255) / 256, 256>>>(key,   xkh, xkl, act4);
    split_bf16_kernel<<<(act4 + 255) / 256, 256>>>(value, xvh, xvl, act4);
    split_bf16_kernel<<<(w4 + 255) / 256, 256>>>(wq, wqh, wql, w4);
    split_bf16_kernel<<<(w4 + 255) / 256, 256>>>(wk, wkh, wkl, w4);
    split_bf16_kernel<<<(w4 + 255) / 256, 256>>>(wv, wvh, wvl, w4);
    split_bf16_kernel<<<(w4 + 255) / 256, 256>>>(wo, woh, wol, w4);

    cudaFuncSetAttribute(gemm_cp_kernel, cudaFuncAttributeMaxDynamicSharedMemorySize,
                         GSMEM);
    dim3 gg(32, 8);
    gemm_cp_kernel<<<gg, 256, GSMEM>>>(xqh, xql, wqh, wql, bq, SCALING, 1,
                                       nullptr, qh, ql);
    gemm_cp_kernel<<<gg, 256, GSMEM>>>(xkh, xkl, wkh, wkl, bk, 1.0f, 1,
                                       nullptr, kh, kl);
    gemm_cp_kernel<<<gg, 256, GSMEM>>>(xvh, xvl, wvh, wvl, bv, 1.0f, 1,
                                       nullptr, vh, vl);

    const int flash_smem = 6 * FBUF + 64 * (int)sizeof(float);
    cudaFuncSetAttribute(flash_mma_kernel,
                         cudaFuncAttributeMaxDynamicSharedMemorySize, flash_smem);
    flash_mma_kernel<<<dim3(16, 16, 4), 128, flash_smem>>>(attn_bias);

    gemm_cp_kernel<<<gg, 256, GSMEM>>>(cxh, cxl, woh, wol, bo, 1.0f, 0,
                                       out, nullptr, nullptr);
}